// round 1
// baseline (speedup 1.0000x reference)
#include <cuda_runtime.h>
#include <math.h>

#define B_ 8
#define N_ 1024
#define C_ 512
#define H_ 8
#define D_ 64
#define S2_ 1024   // 2*SPAN

// ---------------- scratch (static device arrays; no allocation) -------------
__device__ float g_Q[(size_t)B_ * N_ * C_];
__device__ float g_K[(size_t)B_ * N_ * C_];
__device__ float g_V[(size_t)B_ * N_ * C_];
__device__ float g_posK[(size_t)S2_ * C_];
__device__ float g_posQ[(size_t)S2_ * C_];
__device__ float g_S2[(size_t)B_ * H_ * N_ * S2_];   // 256 MB
__device__ float g_S3[(size_t)B_ * H_ * N_ * S2_];   // 256 MB
__device__ float g_SC[(size_t)B_ * H_ * N_ * N_];    // 256 MB

// ---------------- GEMM: Y[M,512] = X[M,512] @ W[512,512] + b ----------------
// 128x128 tile, BK=8, 256 threads, 8x8 per thread.
__global__ __launch_bounds__(256) void sgemm_bias(
    const float* __restrict__ X, const float* __restrict__ W,
    const float* __restrict__ bias, float* __restrict__ Y)
{
    __shared__ float As[8][128];
    __shared__ float Bs[8][128];
    const int tid = threadIdx.x;
    const int tx = tid & 15, ty = tid >> 4;
    const int m0 = blockIdx.y << 7, n0 = blockIdx.x << 7;

    float acc[8][8];
#pragma unroll
    for (int i = 0; i < 8; i++)
#pragma unroll
        for (int j = 0; j < 8; j++) acc[i][j] = 0.f;

    const int arow = tid >> 1, aseg = (tid & 1) << 2;
    const int brow = tid >> 5, bcol = (tid & 31) << 2;

    for (int k0 = 0; k0 < 512; k0 += 8) {
        float4 av = *(const float4*)&X[(size_t)(m0 + arow) * 512 + k0 + aseg];
        float4 bv = *(const float4*)&W[(size_t)(k0 + brow) * 512 + n0 + bcol];
        As[aseg + 0][arow] = av.x;
        As[aseg + 1][arow] = av.y;
        As[aseg + 2][arow] = av.z;
        As[aseg + 3][arow] = av.w;
        *(float4*)&Bs[brow][bcol] = bv;
        __syncthreads();
#pragma unroll
        for (int kk = 0; kk < 8; kk++) {
            float a[8], b[8];
            *(float4*)&a[0] = *(const float4*)&As[kk][ty << 3];
            *(float4*)&a[4] = *(const float4*)&As[kk][(ty << 3) + 4];
            *(float4*)&b[0] = *(const float4*)&Bs[kk][tx << 3];
            *(float4*)&b[4] = *(const float4*)&Bs[kk][(tx << 3) + 4];
#pragma unroll
            for (int i = 0; i < 8; i++)
#pragma unroll
                for (int j = 0; j < 8; j++)
                    acc[i][j] += a[i] * b[j];
        }
        __syncthreads();
    }
#pragma unroll
    for (int i = 0; i < 8; i++) {
        float* yrow = &Y[(size_t)(m0 + (ty << 3) + i) * 512 + n0 + (tx << 3)];
        const float* br = &bias[n0 + (tx << 3)];
#pragma unroll
        for (int j = 0; j < 8; j += 4) {
            float4 o;
            o.x = acc[i][j + 0] + br[j + 0];
            o.y = acc[i][j + 1] + br[j + 1];
            o.z = acc[i][j + 2] + br[j + 2];
            o.w = acc[i][j + 3] + br[j + 3];
            *(float4*)&yrow[j] = o;
        }
    }
}

// Load a 64x64 fp32 tile (row stride rs) transposed into dst[col][row].
__device__ __forceinline__ void load_tile_T(
    const float* __restrict__ src, int rs, float dst[64][68], int tid)
{
#pragma unroll
    for (int i = 0; i < 4; i++) {
        int f4 = (i << 8) + tid;
        int row = f4 >> 4;
        int c = (f4 & 15) << 2;
        float4 v = *(const float4*)&src[(size_t)row * rs + c];
        dst[c + 0][row] = v.x;
        dst[c + 1][row] = v.y;
        dst[c + 2][row] = v.z;
        dst[c + 3][row] = v.w;
    }
}

// ---- S2/S3: OUT[z, i, p] = sum_d A[b, i, h*64+d] * P[p, h*64+d] -----------
__global__ __launch_bounds__(256) void pos_scores(
    const float* __restrict__ A, const float* __restrict__ P,
    float* __restrict__ OUT)
{
    __shared__ float As[64][68];
    __shared__ float Ps[64][68];
    const int z = blockIdx.z, b = z >> 3, h = z & 7;
    const int q0 = blockIdx.y << 6, p0 = blockIdx.x << 6;
    const int tid = threadIdx.x, tx = tid & 15, ty = tid >> 4;

    load_tile_T(A + ((size_t)b * N_ + q0) * C_ + h * D_, C_, As, tid);
    load_tile_T(P + (size_t)p0 * C_ + h * D_, C_, Ps, tid);
    __syncthreads();

    float acc[4][4];
#pragma unroll
    for (int i = 0; i < 4; i++)
#pragma unroll
        for (int j = 0; j < 4; j++) acc[i][j] = 0.f;

#pragma unroll 16
    for (int kk = 0; kk < 64; kk++) {
        float a[4], p[4];
        *(float4*)a = *(const float4*)&As[kk][ty << 2];
        *(float4*)p = *(const float4*)&Ps[kk][tx << 2];
#pragma unroll
        for (int i = 0; i < 4; i++)
#pragma unroll
            for (int j = 0; j < 4; j++)
                acc[i][j] += a[i] * p[j];
    }
#pragma unroll
    for (int i = 0; i < 4; i++) {
        float4 o = make_float4(acc[i][0], acc[i][1], acc[i][2], acc[i][3]);
        *(float4*)&OUT[((size_t)z * N_ + q0 + (ty << 2) + i) * S2_ + p0 + (tx << 2)] = o;
    }
}

// ---- scores: SC[z,q,k] = (Q.K + S2[z,q,idx] + S3[z,k,idx]) / sqrt(192) ----
__global__ __launch_bounds__(256) void qk_scores(
    const float* __restrict__ Q, const float* __restrict__ K,
    const float* __restrict__ S2, const float* __restrict__ S3,
    float* __restrict__ OUT)
{
    __shared__ float Qs[64][68];
    __shared__ float Ks[64][68];
    const int z = blockIdx.z, b = z >> 3, h = z & 7;
    const int q0 = blockIdx.y << 6, k0 = blockIdx.x << 6;
    const int tid = threadIdx.x, tx = tid & 15, ty = tid >> 4;

    load_tile_T(Q + ((size_t)b * N_ + q0) * C_ + h * D_, C_, Qs, tid);
    load_tile_T(K + ((size_t)b * N_ + k0) * C_ + h * D_, C_, Ks, tid);
    __syncthreads();

    float acc[4][4];
#pragma unroll
    for (int i = 0; i < 4; i++)
#pragma unroll
        for (int j = 0; j < 4; j++) acc[i][j] = 0.f;

#pragma unroll 16
    for (int kk = 0; kk < 64; kk++) {
        float a[4], p[4];
        *(float4*)a = *(const float4*)&Qs[kk][ty << 2];
        *(float4*)p = *(const float4*)&Ks[kk][tx << 2];
#pragma unroll
        for (int i = 0; i < 4; i++)
#pragma unroll
            for (int j = 0; j < 4; j++)
                acc[i][j] += a[i] * p[j];
    }

    const float inv_scale = 0.07216878364870323f;  // 1/sqrt(64*3)
#pragma unroll
    for (int i = 0; i < 4; i++) {
        int qq = q0 + (ty << 2) + i;
        float res[4];
#pragma unroll
        for (int j = 0; j < 4; j++) {
            int kc = k0 + (tx << 2) + j;
            int idx = qq - kc + 512;
            idx = idx < 0 ? 0 : (idx > 1023 ? 1023 : idx);
            res[j] = (acc[i][j]
                      + S2[((size_t)z * N_ + qq) * S2_ + idx]
                      + S3[((size_t)z * N_ + kc) * S2_ + idx]) * inv_scale;
        }
        *(float4*)&OUT[((size_t)z * N_ + qq) * N_ + k0 + (tx << 2)] =
            make_float4(res[0], res[1], res[2], res[3]);
    }
}

// ---------------- softmax over last dim (rows of 1024) ----------------------
__global__ __launch_bounds__(256) void softmax_rows(float* __restrict__ S)
{
    float* p = S + (size_t)blockIdx.x * N_;
    const int tid = threadIdx.x;
    const int lane = tid & 31, wid = tid >> 5;
    __shared__ float sh[8];

    float v[4];
    float m = -1e30f;
#pragma unroll
    for (int i = 0; i < 4; i++) {
        v[i] = p[tid + (i << 8)];
        m = fmaxf(m, v[i]);
    }
#pragma unroll
    for (int o = 16; o > 0; o >>= 1) m = fmaxf(m, __shfl_xor_sync(0xffffffffu, m, o));
    if (lane == 0) sh[wid] = m;
    __syncthreads();
    float mall = sh[0];
#pragma unroll
    for (int i = 1; i < 8; i++) mall = fmaxf(mall, sh[i]);

    float s = 0.f;
#pragma unroll
    for (int i = 0; i < 4; i++) {
        v[i] = __expf(v[i] - mall);
        s += v[i];
    }
#pragma unroll
    for (int o = 16; o > 0; o >>= 1) s += __shfl_xor_sync(0xffffffffu, s, o);
    __syncthreads();
    if (lane == 0) sh[wid] = s;
    __syncthreads();
    float sall = 0.f;
#pragma unroll
    for (int i = 0; i < 8; i++) sall += sh[i];
    float inv = 1.f / sall;
#pragma unroll
    for (int i = 0; i < 4; i++) p[tid + (i << 8)] = v[i] * inv;
}

// ---------------- ctx = P @ V, written as [B, N, C] -------------------------
__global__ __launch_bounds__(256) void pv_kernel(
    const float* __restrict__ S, const float* __restrict__ V,
    float* __restrict__ OUT)
{
    __shared__ float Ps[64][68];
    __shared__ float Vs[64][68];
    const int z = blockIdx.y, b = z >> 3, h = z & 7;
    const int q0 = blockIdx.x << 6;
    const int tid = threadIdx.x, tx = tid & 15, ty = tid >> 4;

    float acc[4][4];
#pragma unroll
    for (int i = 0; i < 4; i++)
#pragma unroll
        for (int j = 0; j < 4; j++) acc[i][j] = 0.f;

    for (int k0 = 0; k0 < N_; k0 += 64) {
        // P tile transposed: Ps[k][q]
        load_tile_T(S + ((size_t)z * N_ + q0) * N_ + k0, N_, Ps, tid);
        // V tile natural: Vs[k][j]
#pragma unroll
        for (int i = 0; i < 4; i++) {
            int f4 = (i << 8) + tid;
            int row = f4 >> 4;
            int c = (f4 & 15) << 2;
            float4 vv = *(const float4*)&V[((size_t)b * N_ + k0 + row) * C_ + h * D_ + c];
            Vs[row][c + 0] = vv.x;
            Vs[row][c + 1] = vv.y;
            Vs[row][c + 2] = vv.z;
            Vs[row][c + 3] = vv.w;
        }
        __syncthreads();
#pragma unroll 16
        for (int kk = 0; kk < 64; kk++) {
            float a[4], bb[4];
            *(float4*)a = *(const float4*)&Ps[kk][ty << 2];
            *(float4*)bb = *(const float4*)&Vs[kk][tx << 2];
#pragma unroll
            for (int i = 0; i < 4; i++)
#pragma unroll
                for (int j = 0; j < 4; j++)
                    acc[i][j] += a[i] * bb[j];
        }
        __syncthreads();
    }
#pragma unroll
    for (int i = 0; i < 4; i++) {
        float4 o = make_float4(acc[i][0], acc[i][1], acc[i][2], acc[i][3]);
        *(float4*)&OUT[((size_t)b * N_ + q0 + (ty << 2) + i) * C_ + h * D_ + (tx << 2)] = o;
    }
}

// ---------------------------------------------------------------------------
extern "C" void kernel_launch(void* const* d_in, const int* in_sizes, int n_in,
                              void* d_out, int out_size)
{
    const float* q   = (const float*)d_in[0];
    const float* k   = (const float*)d_in[1];
    const float* val = (const float*)d_in[2];
    const float* rel = (const float*)d_in[3];
    const float* Wq  = (const float*)d_in[4];
    const float* bq  = (const float*)d_in[5];
    const float* Wk  = (const float*)d_in[6];
    const float* bk  = (const float*)d_in[7];
    const float* Wv  = (const float*)d_in[8];
    const float* bv  = (const float*)d_in[9];
    float* out = (float*)d_out;

    float *pQ, *pK, *pV, *pPK, *pPQ, *pS2, *pS3, *pSC;
    cudaGetSymbolAddress((void**)&pQ,  g_Q);
    cudaGetSymbolAddress((void**)&pK,  g_K);
    cudaGetSymbolAddress((void**)&pV,  g_V);
    cudaGetSymbolAddress((void**)&pPK, g_posK);
    cudaGetSymbolAddress((void**)&pPQ, g_posQ);
    cudaGetSymbolAddress((void**)&pS2, g_S2);
    cudaGetSymbolAddress((void**)&pS3, g_S3);
    cudaGetSymbolAddress((void**)&pSC, g_SC);

    dim3 blk(256);
    // Projections
    sgemm_bias<<<dim3(4, 64), blk>>>(q,   Wq, bq, pQ);
    sgemm_bias<<<dim3(4, 64), blk>>>(k,   Wk, bk, pK);
    sgemm_bias<<<dim3(4, 64), blk>>>(val, Wv, bv, pV);
    sgemm_bias<<<dim3(4, 8),  blk>>>(rel, Wk, bk, pPK);  // posK (share_att_key)
    sgemm_bias<<<dim3(4, 8),  blk>>>(rel, Wq, bq, pPQ);  // posQ

    // Position score matrices
    pos_scores<<<dim3(16, 16, 64), blk>>>(pQ, pPK, pS2);  // c2p full
    pos_scores<<<dim3(16, 16, 64), blk>>>(pK, pPQ, pS3);  // p2c full

    // Combined scores (QK^T + gathered c2p + gathered p2c) / sqrt(192)
    qk_scores<<<dim3(16, 16, 64), blk>>>(pQ, pK, pS2, pS3, pSC);

    // Softmax over k
    softmax_rows<<<B_ * H_ * N_, blk>>>(pSC);

    // ctx = P @ V  -> [B, N, C]
    pv_kernel<<<dim3(16, 64), blk>>>(pSC, pV, out);
}

// round 3
// speedup vs baseline: 1.3153x; 1.3153x over previous
#include <cuda_runtime.h>
#include <math.h>

#define B_ 8
#define N_ 1024
#define C_ 512
#define H_ 8
#define D_ 64
#define S2_ 1024   // 2*SPAN

#define INV_SCALE 0.07216878364870323f   // 1/sqrt(64*3)

// ---------------- scratch (static device arrays; no allocation) -------------
__device__ float g_Q[(size_t)B_ * N_ * C_];
__device__ float g_K[(size_t)B_ * N_ * C_];
__device__ float g_V[(size_t)B_ * N_ * C_];
__device__ float g_posK[(size_t)S2_ * C_];
__device__ float g_posQ[(size_t)S2_ * C_];
__device__ float g_S2[(size_t)B_ * H_ * N_ * S2_];   // 256 MB (prescaled)
__device__ float g_S3[(size_t)B_ * H_ * N_ * S2_];   // 256 MB (prescaled)

// ============================================================================
// Merged projections: one launch for Q,K,V (M=8192 each) + posK,posQ (M=1024)
// 128x128 tile, BK=8, 256 threads, 8x8 per thread.
// grid = (4, 208): y<64 Q, y<128 K, y<192 V, y<200 posK, y<208 posQ
// ============================================================================
__global__ __launch_bounds__(256) void proj_all(
    const float* __restrict__ q, const float* __restrict__ k,
    const float* __restrict__ val, const float* __restrict__ rel,
    const float* __restrict__ Wq, const float* __restrict__ bq,
    const float* __restrict__ Wk, const float* __restrict__ bk,
    const float* __restrict__ Wv, const float* __restrict__ bv,
    float* __restrict__ pQ, float* __restrict__ pK, float* __restrict__ pV,
    float* __restrict__ pPK, float* __restrict__ pPQ)
{
    __shared__ float As[8][128];
    __shared__ float Bs[8][128];
    const int tid = threadIdx.x;
    const int tx = tid & 15, ty = tid >> 4;

    const int gy = blockIdx.y;
    const float *X, *W, *bias;
    float* Y;
    int mb;
    if (gy < 64)       { X = q;   W = Wq; bias = bq; Y = pQ;  mb = gy; }
    else if (gy < 128) { X = k;   W = Wk; bias = bk; Y = pK;  mb = gy - 64; }
    else if (gy < 192) { X = val; W = Wv; bias = bv; Y = pV;  mb = gy - 128; }
    else if (gy < 200) { X = rel; W = Wk; bias = bk; Y = pPK; mb = gy - 192; }
    else               { X = rel; W = Wq; bias = bq; Y = pPQ; mb = gy - 200; }

    const int m0 = mb << 7, n0 = blockIdx.x << 7;

    float acc[8][8];
#pragma unroll
    for (int i = 0; i < 8; i++)
#pragma unroll
        for (int j = 0; j < 8; j++) acc[i][j] = 0.f;

    const int arow = tid >> 1, aseg = (tid & 1) << 2;
    const int brow = tid >> 5, bcol = (tid & 31) << 2;

    for (int k0 = 0; k0 < 512; k0 += 8) {
        float4 av = *(const float4*)&X[(size_t)(m0 + arow) * 512 + k0 + aseg];
        float4 bv2 = *(const float4*)&W[(size_t)(k0 + brow) * 512 + n0 + bcol];
        As[aseg + 0][arow] = av.x;
        As[aseg + 1][arow] = av.y;
        As[aseg + 2][arow] = av.z;
        As[aseg + 3][arow] = av.w;
        *(float4*)&Bs[brow][bcol] = bv2;
        __syncthreads();
#pragma unroll
        for (int kk = 0; kk < 8; kk++) {
            float a[8], b[8];
            *(float4*)&a[0] = *(const float4*)&As[kk][ty << 3];
            *(float4*)&a[4] = *(const float4*)&As[kk][(ty << 3) + 4];
            *(float4*)&b[0] = *(const float4*)&Bs[kk][tx << 3];
            *(float4*)&b[4] = *(const float4*)&Bs[kk][(tx << 3) + 4];
#pragma unroll
            for (int i = 0; i < 8; i++)
#pragma unroll
                for (int j = 0; j < 8; j++)
                    acc[i][j] += a[i] * b[j];
        }
        __syncthreads();
    }
#pragma unroll
    for (int i = 0; i < 8; i++) {
        float* yrow = &Y[(size_t)(m0 + (ty << 3) + i) * 512 + n0 + (tx << 3)];
        const float* br = &bias[n0 + (tx << 3)];
#pragma unroll
        for (int j = 0; j < 8; j += 4) {
            float4 o;
            o.x = acc[i][j + 0] + br[j + 0];
            o.y = acc[i][j + 1] + br[j + 1];
            o.z = acc[i][j + 2] + br[j + 2];
            o.w = acc[i][j + 3] + br[j + 3];
            *(float4*)&yrow[j] = o;
        }
    }
}

// ============================================================================
// S2/S3 in one kernel. 128x128 tiles, 8x8 micro, K=64 single pass.
// S2[z,q,p] = Q[b,q,h]·posK[p,h] * INV_SCALE    (z < 64)
// S3[z,k,p] = K[b,k,h]·posQ[p,h] * INV_SCALE    (z >= 64)
// Both are gathered at p = clip(q - k + 512):
//   S2 rows indexed by q -> diagonal band      |bx - by| <= 4
//   S3 rows indexed by k -> anti-diagonal band 3 <= bx + by <= 11
// ============================================================================
__global__ __launch_bounds__(256) void pos_kernel(
    const float* __restrict__ Q, const float* __restrict__ K,
    const float* __restrict__ posK, const float* __restrict__ posQ,
    float* __restrict__ S2, float* __restrict__ S3)
{
    const int by = blockIdx.y, bx = blockIdx.x;
    const int z = blockIdx.z;
    const bool isS3 = z >= 64;
    if (!isS3) {
        if (bx > by + 4 || by > bx + 4) return;        // S2 diagonal band
    } else {
        int s = bx + by;
        if (s < 3 || s > 11) return;                   // S3 anti-diagonal band
    }

    extern __shared__ float sm[];
    float (*As)[132] = (float(*)[132])sm;
    float (*Ps)[132] = (float(*)[132])(sm + 64 * 132);

    const int zz = isS3 ? z - 64 : z;
    const int b = zz >> 3, h = zz & 7;
    const int m0 = by << 7, n0 = bx << 7;
    const int tid = threadIdx.x, tx = tid & 15, ty = tid >> 4;

    const float* A = (isS3 ? K : Q) + ((size_t)(b * N_ + m0)) * C_ + h * D_;
    const float* P = (isS3 ? posQ : posK) + (size_t)n0 * C_ + h * D_;
    float* OUT = (isS3 ? S3 : S2) + (size_t)zz * N_ * S2_;

    // Load both 128x64 tiles transposed: As[d][row], Ps[d][col]
#pragma unroll
    for (int i = 0; i < 8; i++) {
        int f4 = (i << 8) + tid;
        int row = f4 >> 4;
        int c = (f4 & 15) << 2;
        float4 va = *(const float4*)&A[(size_t)row * C_ + c];
        As[c + 0][row] = va.x; As[c + 1][row] = va.y;
        As[c + 2][row] = va.z; As[c + 3][row] = va.w;
        float4 vp = *(const float4*)&P[(size_t)row * C_ + c];
        Ps[c + 0][row] = vp.x; Ps[c + 1][row] = vp.y;
        Ps[c + 2][row] = vp.z; Ps[c + 3][row] = vp.w;
    }
    __syncthreads();

    float acc[8][8];
#pragma unroll
    for (int i = 0; i < 8; i++)
#pragma unroll
        for (int j = 0; j < 8; j++) acc[i][j] = 0.f;

#pragma unroll 8
    for (int kk = 0; kk < 64; kk++) {
        float a[8], bb[8];
        *(float4*)&a[0] = *(const float4*)&As[kk][ty << 3];
        *(float4*)&a[4] = *(const float4*)&As[kk][(ty << 3) + 4];
        *(float4*)&bb[0] = *(const float4*)&Ps[kk][tx << 3];
        *(float4*)&bb[4] = *(const float4*)&Ps[kk][(tx << 3) + 4];
#pragma unroll
        for (int i = 0; i < 8; i++)
#pragma unroll
            for (int j = 0; j < 8; j++)
                acc[i][j] += a[i] * bb[j];
    }

#pragma unroll
    for (int i = 0; i < 8; i++) {
        float* orow = &OUT[(size_t)(m0 + (ty << 3) + i) * S2_ + n0 + (tx << 3)];
#pragma unroll
        for (int j = 0; j < 8; j += 4) {
            float4 o;
            o.x = acc[i][j + 0] * INV_SCALE;
            o.y = acc[i][j + 1] * INV_SCALE;
            o.z = acc[i][j + 2] * INV_SCALE;
            o.w = acc[i][j + 3] * INV_SCALE;
            *(float4*)&orow[j] = o;
        }
    }
}

// ============================================================================
// Fused attention: per CTA one (z, q-tile of 64). Online softmax over k-tiles.
// score(q,k) = Qs·Ks (Q prescaled) + S2[z,q,clip(q-k+512)] + S3[z,k,clip(q-k+512)]
// S2 staged reversed per q-row; S3 staged natural per k-row (both contiguous).
// ============================================================================
#define S3_STRIDE 67
__global__ __launch_bounds__(256) void attn_fused(
    const float* __restrict__ Q, const float* __restrict__ K,
    const float* __restrict__ V, const float* __restrict__ S2,
    const float* __restrict__ S3, float* __restrict__ OUT)
{
    extern __shared__ float sm[];
    float (*Qs)[68]  = (float(*)[68])sm;
    float (*Ks)[68]  = (float(*)[68])(sm + 1 * 64 * 68);   // reused as P[q][k]
    float (*Vs)[68]  = (float(*)[68])(sm + 2 * 64 * 68);
    float (*S2s)[68] = (float(*)[68])(sm + 3 * 64 * 68);
    float (*S3s)[S3_STRIDE] = (float(*)[S3_STRIDE])(sm + 4 * 64 * 68);

    const int z = blockIdx.y, b = z >> 3, h = z & 7;
    const int q0 = blockIdx.x << 6;
    const int tid = threadIdx.x, tx = tid & 15, ty = tid >> 4;

    // Load Q tile transposed + prescaled: Qs[d][q]
    {
        const float* Qp = Q + ((size_t)(b * N_ + q0)) * C_ + h * D_;
#pragma unroll
        for (int i = 0; i < 4; i++) {
            int f4 = (i << 8) + tid;
            int row = f4 >> 4;
            int c = (f4 & 15) << 2;
            float4 v = *(const float4*)&Qp[(size_t)row * C_ + c];
            Qs[c + 0][row] = v.x * INV_SCALE;
            Qs[c + 1][row] = v.y * INV_SCALE;
            Qs[c + 2][row] = v.z * INV_SCALE;
            Qs[c + 3][row] = v.w * INV_SCALE;
        }
    }

    float acc[4][4];
    float m_i[4], l_i[4];
#pragma unroll
    for (int i = 0; i < 4; i++) {
        m_i[i] = -1e30f; l_i[i] = 0.f;
#pragma unroll
        for (int j = 0; j < 4; j++) acc[i][j] = 0.f;
    }

    const int sr = tid >> 2;          // 0..63: staging row
    const int st0 = (tid & 3) << 4;   // 0,16,32,48

    for (int k0 = 0; k0 < N_; k0 += 64) {
        // ---- loads ----
        const float* Kp = K + ((size_t)(b * N_ + k0)) * C_ + h * D_;
        const float* Vp = V + ((size_t)(b * N_ + k0)) * C_ + h * D_;
#pragma unroll
        for (int i = 0; i < 4; i++) {
            int f4 = (i << 8) + tid;
            int row = f4 >> 4;
            int c = (f4 & 15) << 2;
            float4 v = *(const float4*)&Kp[(size_t)row * C_ + c];
            Ks[c + 0][row] = v.x; Ks[c + 1][row] = v.y;
            Ks[c + 2][row] = v.z; Ks[c + 3][row] = v.w;
            float4 w = *(const float4*)&Vp[(size_t)row * C_ + c];
            *(float4*)&Vs[row][c] = w;
        }
        // Gather staging:
        //  S2s[qi][t] = S2[z, q0+qi, clip(q0+qi - k0 - 63 + t + 512)]  (reversed)
        //  S3s[kj][t] = S3[z, k0+kj, clip(q0 + t - (k0+kj) + 512)]     (natural)
        {
            int qq = q0 + sr;
            const float* s2row = S2 + ((size_t)z * N_ + qq) * S2_;
            int base2 = qq - k0 - 63 + 512;
            int kr = k0 + sr;
            const float* s3row = S3 + ((size_t)z * N_ + kr) * S2_;
            int base3 = q0 - kr + 512;
#pragma unroll
            for (int t = 0; t < 16; t++) {
                int i2 = base2 + st0 + t;
                i2 = i2 < 0 ? 0 : (i2 > 1023 ? 1023 : i2);
                S2s[sr][st0 + t] = s2row[i2];
                int i3 = base3 + st0 + t;
                i3 = i3 < 0 ? 0 : (i3 > 1023 ? 1023 : i3);
                S3s[sr][st0 + t] = s3row[i3];
            }
        }
        __syncthreads();

        // ---- S = Qs·Ks ----
        float s[4][4];
#pragma unroll
        for (int i = 0; i < 4; i++)
#pragma unroll
            for (int j = 0; j < 4; j++) s[i][j] = 0.f;
#pragma unroll 16
        for (int kk = 0; kk < 64; kk++) {
            float a[4], bb[4];
            *(float4*)a = *(const float4*)&Qs[kk][ty << 2];
            *(float4*)bb = *(const float4*)&Ks[kk][tx << 2];
#pragma unroll
            for (int i = 0; i < 4; i++)
#pragma unroll
                for (int j = 0; j < 4; j++)
                    s[i][j] += a[i] * bb[j];
        }
        // add position terms: S2s[qi][63-kj] + S3s[kj][qi]
#pragma unroll
        for (int i = 0; i < 4; i++) {
            int qi = (ty << 2) + i;
#pragma unroll
            for (int j = 0; j < 4; j++) {
                int kj = (tx << 2) + j;
                s[i][j] += S2s[qi][63 - kj] + S3s[kj][qi];
            }
        }

        // ---- online softmax ----
        float mt[4], alpha[4], rs[4];
#pragma unroll
        for (int i = 0; i < 4; i++) {
            mt[i] = fmaxf(fmaxf(s[i][0], s[i][1]), fmaxf(s[i][2], s[i][3]));
#pragma unroll
            for (int o = 8; o > 0; o >>= 1)
                mt[i] = fmaxf(mt[i], __shfl_xor_sync(0xffffffffu, mt[i], o));
            float mn = fmaxf(m_i[i], mt[i]);
            alpha[i] = __expf(m_i[i] - mn);
            m_i[i] = mn;
        }
#pragma unroll
        for (int i = 0; i < 4; i++) {
            rs[i] = 0.f;
#pragma unroll
            for (int j = 0; j < 4; j++) {
                s[i][j] = __expf(s[i][j] - m_i[i]);
                rs[i] += s[i][j];
            }
#pragma unroll
            for (int o = 8; o > 0; o >>= 1)
                rs[i] += __shfl_xor_sync(0xffffffffu, rs[i], o);
            l_i[i] = l_i[i] * alpha[i] + rs[i];
#pragma unroll
            for (int j = 0; j < 4; j++) acc[i][j] *= alpha[i];
        }

        __syncthreads();  // QK done; safe to overwrite Ks with P
        // store P natural: P[q][k] into Ks buffer
#pragma unroll
        for (int i = 0; i < 4; i++)
            *(float4*)&Ks[(ty << 2) + i][tx << 2] = *(float4*)&s[i][0];
        __syncthreads();

        // ---- acc += P·V ----
#pragma unroll 16
        for (int kk = 0; kk < 64; kk++) {
            float a[4], bb[4];
#pragma unroll
            for (int i = 0; i < 4; i++) a[i] = Ks[(ty << 2) + i][kk];  // broadcast
            *(float4*)bb = *(const float4*)&Vs[kk][tx << 2];
#pragma unroll
            for (int i = 0; i < 4; i++)
#pragma unroll
                for (int j = 0; j < 4; j++)
                    acc[i][j] += a[i] * bb[j];
        }
        __syncthreads();  // before next iteration's loads
    }

    // ---- epilogue: divide by l, write [B,N,C] ----
#pragma unroll
    for (int i = 0; i < 4; i++) {
        float inv = 1.f / l_i[i];
        float4 o;
        o.x = acc[i][0] * inv; o.y = acc[i][1] * inv;
        o.z = acc[i][2] * inv; o.w = acc[i][3] * inv;
        *(float4*)&OUT[(size_t)(b * N_ + q0 + (ty << 2) + i) * C_ + h * D_ + (tx << 2)] = o;
    }
}

// ---------------------------------------------------------------------------
extern "C" void kernel_launch(void* const* d_in, const int* in_sizes, int n_in,
                              void* d_out, int out_size)
{
    const float* q   = (const float*)d_in[0];
    const float* k   = (const float*)d_in[1];
    const float* val = (const float*)d_in[2];
    const float* rel = (const float*)d_in[3];
    const float* Wq  = (const float*)d_in[4];
    const float* bq  = (const float*)d_in[5];
    const float* Wk  = (const float*)d_in[6];
    const float* bk  = (const float*)d_in[7];
    const float* Wv  = (const float*)d_in[8];
    const float* bv  = (const float*)d_in[9];
    float* out = (float*)d_out;

    float *pQ, *pK, *pV, *pPK, *pPQ, *pS2, *pS3;
    cudaGetSymbolAddress((void**)&pQ,  g_Q);
    cudaGetSymbolAddress((void**)&pK,  g_K);
    cudaGetSymbolAddress((void**)&pV,  g_V);
    cudaGetSymbolAddress((void**)&pPK, g_posK);
    cudaGetSymbolAddress((void**)&pPQ, g_posQ);
    cudaGetSymbolAddress((void**)&pS2, g_S2);
    cudaGetSymbolAddress((void**)&pS3, g_S3);

    static int attr_done = 0;
    if (!attr_done) {
        cudaFuncSetAttribute(pos_kernel,
            cudaFuncAttributeMaxDynamicSharedMemorySize, 2 * 64 * 132 * 4);
        cudaFuncSetAttribute(attn_fused,
            cudaFuncAttributeMaxDynamicSharedMemorySize,
            (4 * 64 * 68 + 64 * S3_STRIDE) * 4);
        attr_done = 1;
    }

    dim3 blk(256);
    proj_all<<<dim3(4, 208), blk>>>(q, k, val, rel, Wq, bq, Wk, bk, Wv, bv,
                                    pQ, pK, pV, pPK, pPQ);
    pos_kernel<<<dim3(8, 8, 128), blk, 2 * 64 * 132 * 4>>>(pQ, pK, pPK, pPQ, pS2, pS3);
    attn_fused<<<dim3(16, 64), blk, (4 * 64 * 68 + 64 * S3_STRIDE) * 4>>>(
        pQ, pK, pV, pS2, pS3, out);
}

// round 4
// speedup vs baseline: 2.0018x; 1.5220x over previous
#include <cuda_runtime.h>
#include <math.h>
#include <stdint.h>

#define B_ 8
#define N_ 1024
#define C_ 512
#define H_ 8
#define D_ 64
#define S2_ 1024   // 2*SPAN

#define INV_SCALE 0.07216878364870323f   // 1/sqrt(64*3)

// ---------------- scratch (static device arrays; no allocation) -------------
__device__ float g_Q[(size_t)B_ * N_ * C_];
__device__ float g_K[(size_t)B_ * N_ * C_];
__device__ float g_V[(size_t)B_ * N_ * C_];
__device__ float g_posK[(size_t)S2_ * C_];
__device__ float g_posQ[(size_t)S2_ * C_];
__device__ float g_S2[(size_t)B_ * H_ * N_ * S2_];   // 256 MB (prescaled)
__device__ float g_S3[(size_t)B_ * H_ * N_ * S2_];   // 256 MB (prescaled)

// ---------------- tf32 mma helpers ------------------------------------------
__device__ __forceinline__ uint32_t f2tf32(float x) {
    uint32_t r;
    asm("cvt.rna.tf32.f32 %0, %1;" : "=r"(r) : "f"(x));
    return r;
}

// D(16x8) += A(16x8,row) * B(8x8,col)   [tf32 in, fp32 accum]
__device__ __forceinline__ void mma_tf32(
    float c[4], uint32_t a0, uint32_t a1, uint32_t a2, uint32_t a3,
    uint32_t b0, uint32_t b1)
{
    asm volatile(
        "mma.sync.aligned.m16n8k8.row.col.f32.tf32.tf32.f32 "
        "{%0,%1,%2,%3}, {%4,%5,%6,%7}, {%8,%9}, {%0,%1,%2,%3};"
        : "+f"(c[0]), "+f"(c[1]), "+f"(c[2]), "+f"(c[3])
        : "r"(a0), "r"(a1), "r"(a2), "r"(a3), "r"(b0), "r"(b1));
}

// ============================================================================
// Merged projections (tf32 mma): Y[M,512] = X[M,512] @ W[512,512] + b
// Block 128x128, BK=32, 256 threads (8 warps, each 64x32).
// grid = (4, 208): y<64 Q, y<128 K, y<192 V, y<200 posK, y<208 posQ
// ============================================================================
#define PA_STRIDE 36
#define PB_STRIDE 132
__global__ __launch_bounds__(256) void proj_all(
    const float* __restrict__ q, const float* __restrict__ k,
    const float* __restrict__ val, const float* __restrict__ rel,
    const float* __restrict__ Wq, const float* __restrict__ bq,
    const float* __restrict__ Wk, const float* __restrict__ bk,
    const float* __restrict__ Wv, const float* __restrict__ bv,
    float* __restrict__ pQ, float* __restrict__ pK, float* __restrict__ pV,
    float* __restrict__ pPK, float* __restrict__ pPQ)
{
    __shared__ uint32_t As[128][PA_STRIDE];   // 128 x 32 tf32
    __shared__ uint32_t Bs[32][PB_STRIDE];    // 32 x 128 tf32

    const int tid = threadIdx.x;
    const int warp = tid >> 5, lane = tid & 31;
    const int g = lane >> 2, t = lane & 3;
    const int wm = (warp & 1) << 6;       // 0 / 64
    const int wn = (warp >> 1) << 5;      // 0,32,64,96

    const int gy = blockIdx.y;
    const float *X, *W, *bias;
    float* Y;
    int mb;
    if (gy < 64)       { X = q;   W = Wq; bias = bq; Y = pQ;  mb = gy; }
    else if (gy < 128) { X = k;   W = Wk; bias = bk; Y = pK;  mb = gy - 64; }
    else if (gy < 192) { X = val; W = Wv; bias = bv; Y = pV;  mb = gy - 128; }
    else if (gy < 200) { X = rel; W = Wk; bias = bk; Y = pPK; mb = gy - 192; }
    else               { X = rel; W = Wq; bias = bq; Y = pPQ; mb = gy - 200; }

    const int m0 = mb << 7, n0 = blockIdx.x << 7;

    // per-thread global load coords
    int arow[4], acol[4], brow[4], bcol[4];
#pragma unroll
    for (int i = 0; i < 4; i++) {
        int idx = (i << 8) + tid;
        arow[i] = idx >> 3;  acol[i] = (idx & 7) << 2;     // A: 128 x 8 float4
        brow[i] = idx >> 5;  bcol[i] = (idx & 31) << 2;    // B: 32 x 32 float4
    }

    float c[4][4][4];
#pragma unroll
    for (int mt = 0; mt < 4; mt++)
#pragma unroll
        for (int nt = 0; nt < 4; nt++)
#pragma unroll
            for (int e = 0; e < 4; e++) c[mt][nt][e] = 0.f;

    float4 xa[4], xb[4];
#pragma unroll
    for (int i = 0; i < 4; i++) {
        xa[i] = *(const float4*)&X[(size_t)(m0 + arow[i]) * 512 + acol[i]];
        xb[i] = *(const float4*)&W[(size_t)brow[i] * 512 + n0 + bcol[i]];
    }

    for (int k0 = 0; k0 < 512; k0 += 32) {
#pragma unroll
        for (int i = 0; i < 4; i++) {
            uint4 ua = make_uint4(f2tf32(xa[i].x), f2tf32(xa[i].y),
                                  f2tf32(xa[i].z), f2tf32(xa[i].w));
            *(uint4*)&As[arow[i]][acol[i]] = ua;
            uint4 ub = make_uint4(f2tf32(xb[i].x), f2tf32(xb[i].y),
                                  f2tf32(xb[i].z), f2tf32(xb[i].w));
            *(uint4*)&Bs[brow[i]][bcol[i]] = ub;
        }
        __syncthreads();

        if (k0 + 32 < 512) {
#pragma unroll
            for (int i = 0; i < 4; i++) {
                xa[i] = *(const float4*)&X[(size_t)(m0 + arow[i]) * 512 + k0 + 32 + acol[i]];
                xb[i] = *(const float4*)&W[(size_t)(k0 + 32 + brow[i]) * 512 + n0 + bcol[i]];
            }
        }

#pragma unroll
        for (int k8 = 0; k8 < 32; k8 += 8) {
            uint32_t a[4][4], b[4][2];
#pragma unroll
            for (int mt = 0; mt < 4; mt++) {
                int rb = wm + (mt << 4);
                a[mt][0] = As[rb + g][k8 + t];
                a[mt][1] = As[rb + g + 8][k8 + t];
                a[mt][2] = As[rb + g][k8 + t + 4];
                a[mt][3] = As[rb + g + 8][k8 + t + 4];
            }
#pragma unroll
            for (int nt = 0; nt < 4; nt++) {
                int nb = wn + (nt << 3) + g;
                b[nt][0] = Bs[k8 + t][nb];
                b[nt][1] = Bs[k8 + t + 4][nb];
            }
#pragma unroll
            for (int mt = 0; mt < 4; mt++)
#pragma unroll
                for (int nt = 0; nt < 4; nt++)
                    mma_tf32(c[mt][nt], a[mt][0], a[mt][1], a[mt][2], a[mt][3],
                             b[nt][0], b[nt][1]);
        }
        __syncthreads();
    }

    // epilogue: bias add, float2 stores
#pragma unroll
    for (int mt = 0; mt < 4; mt++) {
        int r0 = m0 + wm + (mt << 4) + g;
#pragma unroll
        for (int nt = 0; nt < 4; nt++) {
            int cb = n0 + wn + (nt << 3) + (t << 1);
            float b0v = bias[cb], b1v = bias[cb + 1];
            float2 o0 = make_float2(c[mt][nt][0] + b0v, c[mt][nt][1] + b1v);
            float2 o1 = make_float2(c[mt][nt][2] + b0v, c[mt][nt][3] + b1v);
            *(float2*)&Y[(size_t)r0 * 512 + cb] = o0;
            *(float2*)&Y[(size_t)(r0 + 8) * 512 + cb] = o1;
        }
    }
}

// ============================================================================
// S2/S3 (tf32 mma). Block 128x128, K=64, 256 threads (8 warps, each 64x32).
// S2[z,q,p] = Q[b,q,h]·posK[p,h] * INV_SCALE    (z < 64)
// S3[z,k,p] = K[b,k,h]·posQ[p,h] * INV_SCALE    (z >= 64)
// Bands: S2 diagonal |bx-by|<=4 ; S3 anti-diagonal 3<=bx+by<=11
// smem: 2 * 128*68*4 = 69632 B
// ============================================================================
#define POS_STRIDE 68
__global__ __launch_bounds__(256) void pos_kernel(
    const float* __restrict__ Q, const float* __restrict__ K,
    const float* __restrict__ posK, const float* __restrict__ posQ,
    float* __restrict__ S2, float* __restrict__ S3)
{
    const int by = blockIdx.y, bx = blockIdx.x;
    const int z = blockIdx.z;
    const bool isS3 = z >= 64;
    if (!isS3) {
        if (bx > by + 4 || by > bx + 4) return;
    } else {
        int s = bx + by;
        if (s < 3 || s > 11) return;
    }

    extern __shared__ uint32_t psm[];
    uint32_t (*As)[POS_STRIDE] = (uint32_t(*)[POS_STRIDE])psm;             // 128 x 64 (rows)
    uint32_t (*Ps)[POS_STRIDE] = (uint32_t(*)[POS_STRIDE])(psm + 128 * POS_STRIDE);

    const int zz = isS3 ? z - 64 : z;
    const int b = zz >> 3, h = zz & 7;
    const int m0 = by << 7, n0 = bx << 7;
    const int tid = threadIdx.x;
    const int warp = tid >> 5, lane = tid & 31;
    const int g = lane >> 2, t = lane & 3;
    const int wm = (warp & 1) << 6;
    const int wn = (warp >> 1) << 5;

    const float* A = (isS3 ? K : Q) + ((size_t)(b * N_ + m0)) * C_ + h * D_;
    const float* P = (isS3 ? posQ : posK) + (size_t)n0 * C_ + h * D_;
    float* OUT = (isS3 ? S3 : S2) + (size_t)zz * N_ * S2_;

    // natural row-major loads, tf32-convert into smem
#pragma unroll
    for (int i = 0; i < 8; i++) {
        int idx = (i << 8) + tid;            // 2048 float4s = 128 rows x 16
        int row = idx >> 4, cc = (idx & 15) << 2;
        float4 va = *(const float4*)&A[(size_t)row * C_ + cc];
        *(uint4*)&As[row][cc] = make_uint4(f2tf32(va.x), f2tf32(va.y),
                                           f2tf32(va.z), f2tf32(va.w));
        float4 vp = *(const float4*)&P[(size_t)row * C_ + cc];
        *(uint4*)&Ps[row][cc] = make_uint4(f2tf32(vp.x), f2tf32(vp.y),
                                           f2tf32(vp.z), f2tf32(vp.w));
    }
    __syncthreads();

    float c[4][4][4];
#pragma unroll
    for (int mt = 0; mt < 4; mt++)
#pragma unroll
        for (int nt = 0; nt < 4; nt++)
#pragma unroll
            for (int e = 0; e < 4; e++) c[mt][nt][e] = 0.f;

#pragma unroll
    for (int k8 = 0; k8 < 64; k8 += 8) {
        uint32_t a[4][4], bfr[4][2];
#pragma unroll
        for (int mt = 0; mt < 4; mt++) {
            int rb = wm + (mt << 4);
            a[mt][0] = As[rb + g][k8 + t];
            a[mt][1] = As[rb + g + 8][k8 + t];
            a[mt][2] = As[rb + g][k8 + t + 4];
            a[mt][3] = As[rb + g + 8][k8 + t + 4];
        }
#pragma unroll
        for (int nt = 0; nt < 4; nt++) {
            int nb = wn + (nt << 3) + g;
            bfr[nt][0] = Ps[nb][k8 + t];       // B[k][n] = P[n][k]
            bfr[nt][1] = Ps[nb][k8 + t + 4];
        }
#pragma unroll
        for (int mt = 0; mt < 4; mt++)
#pragma unroll
            for (int nt = 0; nt < 4; nt++)
                mma_tf32(c[mt][nt], a[mt][0], a[mt][1], a[mt][2], a[mt][3],
                         bfr[nt][0], bfr[nt][1]);
    }

#pragma unroll
    for (int mt = 0; mt < 4; mt++) {
        int r0 = m0 + wm + (mt << 4) + g;
#pragma unroll
        for (int nt = 0; nt < 4; nt++) {
            int cb = n0 + wn + (nt << 3) + (t << 1);
            float2 o0 = make_float2(c[mt][nt][0] * INV_SCALE, c[mt][nt][1] * INV_SCALE);
            float2 o1 = make_float2(c[mt][nt][2] * INV_SCALE, c[mt][nt][3] * INV_SCALE);
            *(float2*)&OUT[(size_t)r0 * S2_ + cb] = o0;
            *(float2*)&OUT[(size_t)(r0 + 8) * S2_ + cb] = o1;
        }
    }
}

// ============================================================================
// Fused attention (unchanged from round 3 — SIMT, proven correct).
// ============================================================================
#define S3_STRIDE 67
__global__ __launch_bounds__(256) void attn_fused(
    const float* __restrict__ Q, const float* __restrict__ K,
    const float* __restrict__ V, const float* __restrict__ S2,
    const float* __restrict__ S3, float* __restrict__ OUT)
{
    extern __shared__ float sm[];
    float (*Qs)[68]  = (float(*)[68])sm;
    float (*Ks)[68]  = (float(*)[68])(sm + 1 * 64 * 68);   // reused as P[q][k]
    float (*Vs)[68]  = (float(*)[68])(sm + 2 * 64 * 68);
    float (*S2s)[68] = (float(*)[68])(sm + 3 * 64 * 68);
    float (*S3s)[S3_STRIDE] = (float(*)[S3_STRIDE])(sm + 4 * 64 * 68);

    const int z = blockIdx.y, b = z >> 3, h = z & 7;
    const int q0 = blockIdx.x << 6;
    const int tid = threadIdx.x, tx = tid & 15, ty = tid >> 4;

    {
        const float* Qp = Q + ((size_t)(b * N_ + q0)) * C_ + h * D_;
#pragma unroll
        for (int i = 0; i < 4; i++) {
            int f4 = (i << 8) + tid;
            int row = f4 >> 4;
            int cc = (f4 & 15) << 2;
            float4 v = *(const float4*)&Qp[(size_t)row * C_ + cc];
            Qs[cc + 0][row] = v.x * INV_SCALE;
            Qs[cc + 1][row] = v.y * INV_SCALE;
            Qs[cc + 2][row] = v.z * INV_SCALE;
            Qs[cc + 3][row] = v.w * INV_SCALE;
        }
    }

    float acc[4][4];
    float m_i[4], l_i[4];
#pragma unroll
    for (int i = 0; i < 4; i++) {
        m_i[i] = -1e30f; l_i[i] = 0.f;
#pragma unroll
        for (int j = 0; j < 4; j++) acc[i][j] = 0.f;
    }

    const int sr = tid >> 2;
    const int st0 = (tid & 3) << 4;

    for (int k0 = 0; k0 < N_; k0 += 64) {
        const float* Kp = K + ((size_t)(b * N_ + k0)) * C_ + h * D_;
        const float* Vp = V + ((size_t)(b * N_ + k0)) * C_ + h * D_;
#pragma unroll
        for (int i = 0; i < 4; i++) {
            int f4 = (i << 8) + tid;
            int row = f4 >> 4;
            int cc = (f4 & 15) << 2;
            float4 v = *(const float4*)&Kp[(size_t)row * C_ + cc];
            Ks[cc + 0][row] = v.x; Ks[cc + 1][row] = v.y;
            Ks[cc + 2][row] = v.z; Ks[cc + 3][row] = v.w;
            float4 w = *(const float4*)&Vp[(size_t)row * C_ + cc];
            *(float4*)&Vs[row][cc] = w;
        }
        {
            int qq = q0 + sr;
            const float* s2row = S2 + ((size_t)z * N_ + qq) * S2_;
            int base2 = qq - k0 - 63 + 512;
            int kr = k0 + sr;
            const float* s3row = S3 + ((size_t)z * N_ + kr) * S2_;
            int base3 = q0 - kr + 512;
#pragma unroll
            for (int tt = 0; tt < 16; tt++) {
                int i2 = base2 + st0 + tt;
                i2 = i2 < 0 ? 0 : (i2 > 1023 ? 1023 : i2);
                S2s[sr][st0 + tt] = s2row[i2];
                int i3 = base3 + st0 + tt;
                i3 = i3 < 0 ? 0 : (i3 > 1023 ? 1023 : i3);
                S3s[sr][st0 + tt] = s3row[i3];
            }
        }
        __syncthreads();

        float s[4][4];
#pragma unroll
        for (int i = 0; i < 4; i++)
#pragma unroll
            for (int j = 0; j < 4; j++) s[i][j] = 0.f;
#pragma unroll 16
        for (int kk = 0; kk < 64; kk++) {
            float a[4], bb[4];
            *(float4*)a = *(const float4*)&Qs[kk][ty << 2];
            *(float4*)bb = *(const float4*)&Ks[kk][tx << 2];
#pragma unroll
            for (int i = 0; i < 4; i++)
#pragma unroll
                for (int j = 0; j < 4; j++)
                    s[i][j] += a[i] * bb[j];
        }
#pragma unroll
        for (int i = 0; i < 4; i++) {
            int qi = (ty << 2) + i;
#pragma unroll
            for (int j = 0; j < 4; j++) {
                int kj = (tx << 2) + j;
                s[i][j] += S2s[qi][63 - kj] + S3s[kj][qi];
            }
        }

        float mt[4], alpha[4], rs[4];
#pragma unroll
        for (int i = 0; i < 4; i++) {
            mt[i] = fmaxf(fmaxf(s[i][0], s[i][1]), fmaxf(s[i][2], s[i][3]));
#pragma unroll
            for (int o = 8; o > 0; o >>= 1)
                mt[i] = fmaxf(mt[i], __shfl_xor_sync(0xffffffffu, mt[i], o));
            float mn = fmaxf(m_i[i], mt[i]);
            alpha[i] = __expf(m_i[i] - mn);
            m_i[i] = mn;
        }
#pragma unroll
        for (int i = 0; i < 4; i++) {
            rs[i] = 0.f;
#pragma unroll
            for (int j = 0; j < 4; j++) {
                s[i][j] = __expf(s[i][j] - m_i[i]);
                rs[i] += s[i][j];
            }
#pragma unroll
            for (int o = 8; o > 0; o >>= 1)
                rs[i] += __shfl_xor_sync(0xffffffffu, rs[i], o);
            l_i[i] = l_i[i] * alpha[i] + rs[i];
#pragma unroll
            for (int j = 0; j < 4; j++) acc[i][j] *= alpha[i];
        }

        __syncthreads();
#pragma unroll
        for (int i = 0; i < 4; i++)
            *(float4*)&Ks[(ty << 2) + i][tx << 2] = *(float4*)&s[i][0];
        __syncthreads();

#pragma unroll 16
        for (int kk = 0; kk < 64; kk++) {
            float a[4], bb[4];
#pragma unroll
            for (int i = 0; i < 4; i++) a[i] = Ks[(ty << 2) + i][kk];
            *(float4*)bb = *(const float4*)&Vs[kk][tx << 2];
#pragma unroll
            for (int i = 0; i < 4; i++)
#pragma unroll
                for (int j = 0; j < 4; j++)
                    acc[i][j] += a[i] * bb[j];
        }
        __syncthreads();
    }

#pragma unroll
    for (int i = 0; i < 4; i++) {
        float inv = 1.f / l_i[i];
        float4 o;
        o.x = acc[i][0] * inv; o.y = acc[i][1] * inv;
        o.z = acc[i][2] * inv; o.w = acc[i][3] * inv;
        *(float4*)&OUT[(size_t)(b * N_ + q0 + (ty << 2) + i) * C_ + h * D_ + (tx << 2)] = o;
    }
}

// ---------------------------------------------------------------------------
extern "C" void kernel_launch(void* const* d_in, const int* in_sizes, int n_in,
                              void* d_out, int out_size)
{
    const float* q   = (const float*)d_in[0];
    const float* k   = (const float*)d_in[1];
    const float* val = (const float*)d_in[2];
    const float* rel = (const float*)d_in[3];
    const float* Wq  = (const float*)d_in[4];
    const float* bq  = (const float*)d_in[5];
    const float* Wk  = (const float*)d_in[6];
    const float* bk  = (const float*)d_in[7];
    const float* Wv  = (const float*)d_in[8];
    const float* bv  = (const float*)d_in[9];
    float* out = (float*)d_out;

    float *pQ, *pK, *pV, *pPK, *pPQ, *pS2, *pS3;
    cudaGetSymbolAddress((void**)&pQ,  g_Q);
    cudaGetSymbolAddress((void**)&pK,  g_K);
    cudaGetSymbolAddress((void**)&pV,  g_V);
    cudaGetSymbolAddress((void**)&pPK, g_posK);
    cudaGetSymbolAddress((void**)&pPQ, g_posQ);
    cudaGetSymbolAddress((void**)&pS2, g_S2);
    cudaGetSymbolAddress((void**)&pS3, g_S3);

    static int attr_done = 0;
    if (!attr_done) {
        cudaFuncSetAttribute(pos_kernel,
            cudaFuncAttributeMaxDynamicSharedMemorySize, 2 * 128 * POS_STRIDE * 4);
        cudaFuncSetAttribute(attn_fused,
            cudaFuncAttributeMaxDynamicSharedMemorySize,
            (4 * 64 * 68 + 64 * S3_STRIDE) * 4);
        attr_done = 1;
    }

    dim3 blk(256);
    proj_all<<<dim3(4, 208), blk>>>(q, k, val, rel, Wq, bq, Wk, bk, Wv, bv,
                                    pQ, pK, pV, pPK, pPQ);
    pos_kernel<<<dim3(8, 8, 128), blk, 2 * 128 * POS_STRIDE * 4>>>(
        pQ, pK, pPK, pPQ, pS2, pS3);
    attn_fused<<<dim3(16, 64), blk, (4 * 64 * 68 + 64 * S3_STRIDE) * 4>>>(
        pQ, pK, pV, pS2, pS3, out);
}

// round 6
// speedup vs baseline: 3.0537x; 1.5255x over previous
#include <cuda_runtime.h>
#include <math.h>
#include <stdint.h>

#define B_ 8
#define N_ 1024
#define C_ 512
#define H_ 8
#define D_ 64
#define S2_ 1024   // 2*SPAN

#define INV_SCALE 0.07216878364870323f   // 1/sqrt(64*3)

// ---------------- scratch (static device arrays; no allocation) -------------
__device__ float g_Q[(size_t)B_ * N_ * C_];
__device__ float g_K[(size_t)B_ * N_ * C_];
__device__ float g_V[(size_t)B_ * N_ * C_];
__device__ float g_posK[(size_t)S2_ * C_];
__device__ float g_posQ[(size_t)S2_ * C_];
__device__ float g_S2[(size_t)B_ * H_ * N_ * S2_];   // prescaled
__device__ float g_S3[(size_t)B_ * H_ * N_ * S2_];   // prescaled

// ---------------- tf32 mma helpers ------------------------------------------
__device__ __forceinline__ uint32_t f2tf32(float x) {
    uint32_t r;
    asm("cvt.rna.tf32.f32 %0, %1;" : "=r"(r) : "f"(x));
    return r;
}

__device__ __forceinline__ void mma_tf32(
    float c[4], uint32_t a0, uint32_t a1, uint32_t a2, uint32_t a3,
    uint32_t b0, uint32_t b1)
{
    asm volatile(
        "mma.sync.aligned.m16n8k8.row.col.f32.tf32.tf32.f32 "
        "{%0,%1,%2,%3}, {%4,%5,%6,%7}, {%8,%9}, {%0,%1,%2,%3};"
        : "+f"(c[0]), "+f"(c[1]), "+f"(c[2]), "+f"(c[3])
        : "r"(a0), "r"(a1), "r"(a2), "r"(a3), "r"(b0), "r"(b1));
}

// ============================================================================
// Merged projections (tf32 mma): Y[M,512] = X[M,512] @ W[512,512] + b
// ============================================================================
#define PA_STRIDE 36
#define PB_STRIDE 132
__global__ __launch_bounds__(256) void proj_all(
    const float* __restrict__ q, const float* __restrict__ k,
    const float* __restrict__ val, const float* __restrict__ rel,
    const float* __restrict__ Wq, const float* __restrict__ bq,
    const float* __restrict__ Wk, const float* __restrict__ bk,
    const float* __restrict__ Wv, const float* __restrict__ bv,
    float* __restrict__ pQ, float* __restrict__ pK, float* __restrict__ pV,
    float* __restrict__ pPK, float* __restrict__ pPQ)
{
    __shared__ uint32_t As[128][PA_STRIDE];
    __shared__ uint32_t Bs[32][PB_STRIDE];

    const int tid = threadIdx.x;
    const int warp = tid >> 5, lane = tid & 31;
    const int g = lane >> 2, t = lane & 3;
    const int wm = (warp & 1) << 6;
    const int wn = (warp >> 1) << 5;

    const int gy = blockIdx.y;
    const float *X, *W, *bias;
    float* Y;
    int mb;
    if (gy < 64)       { X = q;   W = Wq; bias = bq; Y = pQ;  mb = gy; }
    else if (gy < 128) { X = k;   W = Wk; bias = bk; Y = pK;  mb = gy - 64; }
    else if (gy < 192) { X = val; W = Wv; bias = bv; Y = pV;  mb = gy - 128; }
    else if (gy < 200) { X = rel; W = Wk; bias = bk; Y = pPK; mb = gy - 192; }
    else               { X = rel; W = Wq; bias = bq; Y = pPQ; mb = gy - 200; }

    const int m0 = mb << 7, n0 = blockIdx.x << 7;

    int arow[4], acol[4], brow[4], bcol[4];
#pragma unroll
    for (int i = 0; i < 4; i++) {
        int idx = (i << 8) + tid;
        arow[i] = idx >> 3;  acol[i] = (idx & 7) << 2;
        brow[i] = idx >> 5;  bcol[i] = (idx & 31) << 2;
    }

    float c[4][4][4];
#pragma unroll
    for (int mt = 0; mt < 4; mt++)
#pragma unroll
        for (int nt = 0; nt < 4; nt++)
#pragma unroll
            for (int e = 0; e < 4; e++) c[mt][nt][e] = 0.f;

    float4 xa[4], xb[4];
#pragma unroll
    for (int i = 0; i < 4; i++) {
        xa[i] = *(const float4*)&X[(size_t)(m0 + arow[i]) * 512 + acol[i]];
        xb[i] = *(const float4*)&W[(size_t)brow[i] * 512 + n0 + bcol[i]];
    }

    for (int k0 = 0; k0 < 512; k0 += 32) {
#pragma unroll
        for (int i = 0; i < 4; i++) {
            *(uint4*)&As[arow[i]][acol[i]] = make_uint4(
                f2tf32(xa[i].x), f2tf32(xa[i].y), f2tf32(xa[i].z), f2tf32(xa[i].w));
            *(uint4*)&Bs[brow[i]][bcol[i]] = make_uint4(
                f2tf32(xb[i].x), f2tf32(xb[i].y), f2tf32(xb[i].z), f2tf32(xb[i].w));
        }
        __syncthreads();

        if (k0 + 32 < 512) {
#pragma unroll
            for (int i = 0; i < 4; i++) {
                xa[i] = *(const float4*)&X[(size_t)(m0 + arow[i]) * 512 + k0 + 32 + acol[i]];
                xb[i] = *(const float4*)&W[(size_t)(k0 + 32 + brow[i]) * 512 + n0 + bcol[i]];
            }
        }

#pragma unroll
        for (int k8 = 0; k8 < 32; k8 += 8) {
            uint32_t a[4][4], b[4][2];
#pragma unroll
            for (int mt = 0; mt < 4; mt++) {
                int rb = wm + (mt << 4);
                a[mt][0] = As[rb + g][k8 + t];
                a[mt][1] = As[rb + g + 8][k8 + t];
                a[mt][2] = As[rb + g][k8 + t + 4];
                a[mt][3] = As[rb + g + 8][k8 + t + 4];
            }
#pragma unroll
            for (int nt = 0; nt < 4; nt++) {
                int nb = wn + (nt << 3) + g;
                b[nt][0] = Bs[k8 + t][nb];
                b[nt][1] = Bs[k8 + t + 4][nb];
            }
#pragma unroll
            for (int mt = 0; mt < 4; mt++)
#pragma unroll
                for (int nt = 0; nt < 4; nt++)
                    mma_tf32(c[mt][nt], a[mt][0], a[mt][1], a[mt][2], a[mt][3],
                             b[nt][0], b[nt][1]);
        }
        __syncthreads();
    }

#pragma unroll
    for (int mt = 0; mt < 4; mt++) {
        int r0 = m0 + wm + (mt << 4) + g;
#pragma unroll
        for (int nt = 0; nt < 4; nt++) {
            int cb = n0 + wn + (nt << 3) + (t << 1);
            float b0v = bias[cb], b1v = bias[cb + 1];
            *(float2*)&Y[(size_t)r0 * 512 + cb] =
                make_float2(c[mt][nt][0] + b0v, c[mt][nt][1] + b1v);
            *(float2*)&Y[(size_t)(r0 + 8) * 512 + cb] =
                make_float2(c[mt][nt][2] + b0v, c[mt][nt][3] + b1v);
        }
    }
}

// ============================================================================
// S2/S3 (tf32 mma), banded.
// ============================================================================
#define POS_STRIDE 68
__global__ __launch_bounds__(256) void pos_kernel(
    const float* __restrict__ Q, const float* __restrict__ K,
    const float* __restrict__ posK, const float* __restrict__ posQ,
    float* __restrict__ S2, float* __restrict__ S3)
{
    const int by = blockIdx.y, bx = blockIdx.x;
    const int z = blockIdx.z;
    const bool isS3 = z >= 64;
    if (!isS3) {
        if (bx > by + 4 || by > bx + 4) return;
    } else {
        int s = bx + by;
        if (s < 3 || s > 11) return;
    }

    extern __shared__ uint32_t psm[];
    uint32_t (*As)[POS_STRIDE] = (uint32_t(*)[POS_STRIDE])psm;
    uint32_t (*Ps)[POS_STRIDE] = (uint32_t(*)[POS_STRIDE])(psm + 128 * POS_STRIDE);

    const int zz = isS3 ? z - 64 : z;
    const int b = zz >> 3, h = zz & 7;
    const int m0 = by << 7, n0 = bx << 7;
    const int tid = threadIdx.x;
    const int warp = tid >> 5, lane = tid & 31;
    const int g = lane >> 2, t = lane & 3;
    const int wm = (warp & 1) << 6;
    const int wn = (warp >> 1) << 5;

    const float* A = (isS3 ? K : Q) + ((size_t)(b * N_ + m0)) * C_ + h * D_;
    const float* P = (isS3 ? posQ : posK) + (size_t)n0 * C_ + h * D_;
    float* OUT = (isS3 ? S3 : S2) + (size_t)zz * N_ * S2_;

#pragma unroll
    for (int i = 0; i < 8; i++) {
        int idx = (i << 8) + tid;
        int row = idx >> 4, cc = (idx & 15) << 2;
        float4 va = *(const float4*)&A[(size_t)row * C_ + cc];
        *(uint4*)&As[row][cc] = make_uint4(f2tf32(va.x), f2tf32(va.y),
                                           f2tf32(va.z), f2tf32(va.w));
        float4 vp = *(const float4*)&P[(size_t)row * C_ + cc];
        *(uint4*)&Ps[row][cc] = make_uint4(f2tf32(vp.x), f2tf32(vp.y),
                                           f2tf32(vp.z), f2tf32(vp.w));
    }
    __syncthreads();

    float c[4][4][4];
#pragma unroll
    for (int mt = 0; mt < 4; mt++)
#pragma unroll
        for (int nt = 0; nt < 4; nt++)
#pragma unroll
            for (int e = 0; e < 4; e++) c[mt][nt][e] = 0.f;

#pragma unroll
    for (int k8 = 0; k8 < 64; k8 += 8) {
        uint32_t a[4][4], bfr[4][2];
#pragma unroll
        for (int mt = 0; mt < 4; mt++) {
            int rb = wm + (mt << 4);
            a[mt][0] = As[rb + g][k8 + t];
            a[mt][1] = As[rb + g + 8][k8 + t];
            a[mt][2] = As[rb + g][k8 + t + 4];
            a[mt][3] = As[rb + g + 8][k8 + t + 4];
        }
#pragma unroll
        for (int nt = 0; nt < 4; nt++) {
            int nb = wn + (nt << 3) + g;
            bfr[nt][0] = Ps[nb][k8 + t];
            bfr[nt][1] = Ps[nb][k8 + t + 4];
        }
#pragma unroll
        for (int mt = 0; mt < 4; mt++)
#pragma unroll
            for (int nt = 0; nt < 4; nt++)
                mma_tf32(c[mt][nt], a[mt][0], a[mt][1], a[mt][2], a[mt][3],
                         bfr[nt][0], bfr[nt][1]);
    }

#pragma unroll
    for (int mt = 0; mt < 4; mt++) {
        int r0 = m0 + wm + (mt << 4) + g;
#pragma unroll
        for (int nt = 0; nt < 4; nt++) {
            int cb = n0 + wn + (nt << 3) + (t << 1);
            *(float2*)&OUT[(size_t)r0 * S2_ + cb] =
                make_float2(c[mt][nt][0] * INV_SCALE, c[mt][nt][1] * INV_SCALE);
            *(float2*)&OUT[(size_t)(r0 + 8) * S2_ + cb] =
                make_float2(c[mt][nt][2] * INV_SCALE, c[mt][nt][3] * INV_SCALE);
        }
    }
}

// ============================================================================
// Tensor-core fused attention.
// CTA: 128 q-rows x one (b,h). 8 warps; warp w owns q-rows [16w,16w+16).
// Loop over k-tiles of 64: QK via mma (Q prescaled), + S2/S3 gathers from
// global (shared index clip(q-k+512)), FA2 online softmax, P->smem tf32,
// PV via mma. Strides: Qs/Ks/Ps 68, Vs 72 (conflict-free fragment loads).
// ============================================================================
#define AQ_STR 68
#define AV_STR 72
#define ATTN_SMEM ((128*AQ_STR + 64*AQ_STR + 64*AV_STR + 128*AQ_STR) * 4)
__global__ __launch_bounds__(256) void attn_tc(
    const float* __restrict__ Q, const float* __restrict__ K,
    const float* __restrict__ V, const float* __restrict__ S2,
    const float* __restrict__ S3, float* __restrict__ OUT)
{
    extern __shared__ uint32_t asmem[];
    uint32_t (*Qs)[AQ_STR] = (uint32_t(*)[AQ_STR])asmem;                     // [128][68]
    uint32_t (*Ks)[AQ_STR] = (uint32_t(*)[AQ_STR])(asmem + 128 * AQ_STR);    // [64][68]
    uint32_t (*Vs)[AV_STR] = (uint32_t(*)[AV_STR])(asmem + 192 * AQ_STR);    // [64][72]
    uint32_t (*Ps)[AQ_STR] = (uint32_t(*)[AQ_STR])(asmem + 192 * AQ_STR + 64 * AV_STR); // [128][68]

    const int z = blockIdx.y, b = z >> 3, h = z & 7;
    const int q0 = blockIdx.x << 7;
    const int tid = threadIdx.x;
    const int warp = tid >> 5, lane = tid & 31;
    const int g = lane >> 2, t = lane & 3;

    // Load Q tile (128x64), prescale, tf32 into Qs
#pragma unroll
    for (int i = 0; i < 8; i++) {
        int idx = (i << 8) + tid;
        int row = idx >> 4, cc = (idx & 15) << 2;
        float4 v = *(const float4*)&Q[((size_t)(b * N_ + q0 + row)) * C_ + h * D_ + cc];
        *(uint4*)&Qs[row][cc] = make_uint4(
            f2tf32(v.x * INV_SCALE), f2tf32(v.y * INV_SCALE),
            f2tf32(v.z * INV_SCALE), f2tf32(v.w * INV_SCALE));
    }

    const int qrl = (warp << 4) + g;          // local q row (0..127), +8 for second
    const int qg0 = q0 + qrl, qg1 = qg0 + 8;
    const float* s2r0 = S2 + ((size_t)z * N_ + qg0) * S2_;
    const float* s2r1 = s2r0 + (size_t)8 * S2_;
    const float* S3z = S3 + (size_t)z * N_ * S2_;

    float o[8][4];
#pragma unroll
    for (int nt = 0; nt < 8; nt++)
#pragma unroll
        for (int e = 0; e < 4; e++) o[nt][e] = 0.f;
    float m0r = -1e30f, m1r = -1e30f, l0r = 0.f, l1r = 0.f;

    for (int k0 = 0; k0 < N_; k0 += 64) {
        // load K,V tiles (64x64 each)
#pragma unroll
        for (int i = 0; i < 4; i++) {
            int idx = (i << 8) + tid;
            int row = idx >> 4, cc = (idx & 15) << 2;
            float4 kv = *(const float4*)&K[((size_t)(b * N_ + k0 + row)) * C_ + h * D_ + cc];
            *(uint4*)&Ks[row][cc] = make_uint4(f2tf32(kv.x), f2tf32(kv.y),
                                               f2tf32(kv.z), f2tf32(kv.w));
            float4 vv = *(const float4*)&V[((size_t)(b * N_ + k0 + row)) * C_ + h * D_ + cc];
            *(uint4*)&Vs[row][cc] = make_uint4(f2tf32(vv.x), f2tf32(vv.y),
                                               f2tf32(vv.z), f2tf32(vv.w));
        }
        __syncthreads();

        // ---- QK: warp computes 16 x 64 scores ----
        float cf[8][4];
#pragma unroll
        for (int nt = 0; nt < 8; nt++)
#pragma unroll
            for (int e = 0; e < 4; e++) cf[nt][e] = 0.f;
#pragma unroll
        for (int k8 = 0; k8 < 64; k8 += 8) {
            uint32_t a0 = Qs[qrl][k8 + t];
            uint32_t a1 = Qs[qrl + 8][k8 + t];
            uint32_t a2 = Qs[qrl][k8 + t + 4];
            uint32_t a3 = Qs[qrl + 8][k8 + t + 4];
#pragma unroll
            for (int nt = 0; nt < 8; nt++) {
                uint32_t b0 = Ks[(nt << 3) + g][k8 + t];
                uint32_t b1 = Ks[(nt << 3) + g][k8 + t + 4];
                mma_tf32(cf[nt], a0, a1, a2, a3, b0, b1);
            }
        }

        // ---- add position terms (shared index clip(q-k+512)) ----
#pragma unroll
        for (int nt = 0; nt < 8; nt++) {
            int kj = k0 + (nt << 3) + (t << 1);
            const float* s3c0 = S3z + (size_t)kj * S2_;
            const float* s3c1 = s3c0 + S2_;
            int d00 = qg0 - kj + 512;
            int c00 = min(max(d00, 0), 1023);
            int c01 = min(max(d00 - 1, 0), 1023);
            int c10 = min(max(d00 + 8, 0), 1023);
            int c11 = min(max(d00 + 7, 0), 1023);
            cf[nt][0] += s2r0[c00] + s3c0[c00];
            cf[nt][1] += s2r0[c01] + s3c1[c01];
            cf[nt][2] += s2r1[c10] + s3c0[c10];
            cf[nt][3] += s2r1[c11] + s3c1[c11];
        }

        // ---- online softmax (rows qg0, qg1; quad = lanes sharing g) ----
        float tm0 = -1e30f, tm1 = -1e30f;
#pragma unroll
        for (int nt = 0; nt < 8; nt++) {
            tm0 = fmaxf(tm0, fmaxf(cf[nt][0], cf[nt][1]));
            tm1 = fmaxf(tm1, fmaxf(cf[nt][2], cf[nt][3]));
        }
        tm0 = fmaxf(tm0, __shfl_xor_sync(0xffffffffu, tm0, 1));
        tm0 = fmaxf(tm0, __shfl_xor_sync(0xffffffffu, tm0, 2));
        tm1 = fmaxf(tm1, __shfl_xor_sync(0xffffffffu, tm1, 1));
        tm1 = fmaxf(tm1, __shfl_xor_sync(0xffffffffu, tm1, 2));
        float nm0 = fmaxf(m0r, tm0), nm1 = fmaxf(m1r, tm1);
        float al0 = __expf(m0r - nm0), al1 = __expf(m1r - nm1);
        m0r = nm0; m1r = nm1;

        float rs0 = 0.f, rs1 = 0.f;
#pragma unroll
        for (int nt = 0; nt < 8; nt++) {
            cf[nt][0] = __expf(cf[nt][0] - m0r); rs0 += cf[nt][0];
            cf[nt][1] = __expf(cf[nt][1] - m0r); rs0 += cf[nt][1];
            cf[nt][2] = __expf(cf[nt][2] - m1r); rs1 += cf[nt][2];
            cf[nt][3] = __expf(cf[nt][3] - m1r); rs1 += cf[nt][3];
        }
        rs0 += __shfl_xor_sync(0xffffffffu, rs0, 1);
        rs0 += __shfl_xor_sync(0xffffffffu, rs0, 2);
        rs1 += __shfl_xor_sync(0xffffffffu, rs1, 1);
        rs1 += __shfl_xor_sync(0xffffffffu, rs1, 2);
        l0r = l0r * al0 + rs0;
        l1r = l1r * al1 + rs1;
#pragma unroll
        for (int nt = 0; nt < 8; nt++) {
            o[nt][0] *= al0; o[nt][1] *= al0;
            o[nt][2] *= al1; o[nt][3] *= al1;
        }

        // ---- P -> smem (tf32); warp-local rows, warp-sync only ----
#pragma unroll
        for (int nt = 0; nt < 8; nt++) {
            int col = (nt << 3) + (t << 1);
            *(uint2*)&Ps[qrl][col] = make_uint2(f2tf32(cf[nt][0]), f2tf32(cf[nt][1]));
            *(uint2*)&Ps[qrl + 8][col] = make_uint2(f2tf32(cf[nt][2]), f2tf32(cf[nt][3]));
        }
        __syncwarp();

        // ---- o += P · V ----
#pragma unroll
        for (int k8 = 0; k8 < 64; k8 += 8) {
            uint32_t a0 = Ps[qrl][k8 + t];
            uint32_t a1 = Ps[qrl + 8][k8 + t];
            uint32_t a2 = Ps[qrl][k8 + t + 4];
            uint32_t a3 = Ps[qrl + 8][k8 + t + 4];
#pragma unroll
            for (int nt = 0; nt < 8; nt++) {
                uint32_t b0 = Vs[k8 + t][(nt << 3) + g];
                uint32_t b1 = Vs[k8 + t + 4][(nt << 3) + g];
                mma_tf32(o[nt], a0, a1, a2, a3, b0, b1);
            }
        }
        __syncthreads();   // Ks/Vs reused next iteration
    }

    // ---- epilogue ----
    float inv0 = 1.f / l0r, inv1 = 1.f / l1r;
#pragma unroll
    for (int nt = 0; nt < 8; nt++) {
        int col = h * D_ + (nt << 3) + (t << 1);
        *(float2*)&OUT[((size_t)(b * N_ + qg0)) * C_ + col] =
            make_float2(o[nt][0] * inv0, o[nt][1] * inv0);
        *(float2*)&OUT[((size_t)(b * N_ + qg1)) * C_ + col] =
            make_float2(o[nt][2] * inv1, o[nt][3] * inv1);
    }
}

// ---------------------------------------------------------------------------
extern "C" void kernel_launch(void* const* d_in, const int* in_sizes, int n_in,
                              void* d_out, int out_size)
{
    const float* q   = (const float*)d_in[0];
    const float* k   = (const float*)d_in[1];
    const float* val = (const float*)d_in[2];
    const float* rel = (const float*)d_in[3];
    const float* Wq  = (const float*)d_in[4];
    const float* bq  = (const float*)d_in[5];
    const float* Wk  = (const float*)d_in[6];
    const float* bk  = (const float*)d_in[7];
    const float* Wv  = (const float*)d_in[8];
    const float* bv  = (const float*)d_in[9];
    float* out = (float*)d_out;

    float *pQ, *pK, *pV, *pPK, *pPQ, *pS2, *pS3;
    cudaGetSymbolAddress((void**)&pQ,  g_Q);
    cudaGetSymbolAddress((void**)&pK,  g_K);
    cudaGetSymbolAddress((void**)&pV,  g_V);
    cudaGetSymbolAddress((void**)&pPK, g_posK);
    cudaGetSymbolAddress((void**)&pPQ, g_posQ);
    cudaGetSymbolAddress((void**)&pS2, g_S2);
    cudaGetSymbolAddress((void**)&pS3, g_S3);

    static int attr_done = 0;
    if (!attr_done) {
        cudaFuncSetAttribute(pos_kernel,
            cudaFuncAttributeMaxDynamicSharedMemorySize, 2 * 128 * POS_STRIDE * 4);
        cudaFuncSetAttribute(attn_tc,
            cudaFuncAttributeMaxDynamicSharedMemorySize, ATTN_SMEM);
        attr_done = 1;
    }

    dim3 blk(256);
    proj_all<<<dim3(4, 208), blk>>>(q, k, val, rel, Wq, bq, Wk, bk, Wv, bv,
                                    pQ, pK, pV, pPK, pPQ);
    pos_kernel<<<dim3(8, 8, 128), blk, 2 * 128 * POS_STRIDE * 4>>>(
        pQ, pK, pPK, pPQ, pS2, pS3);
    attn_tc<<<dim3(8, 64), blk, ATTN_SMEM>>>(pQ, pK, pV, pS2, pS3, out);
}